// round 14
// baseline (speedup 1.0000x reference)
#include <cuda_runtime.h>
#include <cuda_fp16.h>
#include <cstdint>

#define NN 100000
#define EE 6400000
#define PP 12
#define FF 32
#define ROWH 16    // halves per bank row -> 32B
#define NBANK 8    // accumulation banks per node (f16 rounding error ~ 1/B)
#define DEG_BLOCKS ((EE / 2 + 255) / 256)   // 12500

// scratch (device globals: no allocations allowed; BSS is zero-initialized,
// and each call re-zeroes its scratch after use => every call starts clean)
__device__ __align__(16) float  g_deg[NN];
__device__ __align__(16) float  g_dinv[NN];
__device__ __align__(16) __half g_agg[NN * NBANK * ROWH];   // 25.6 MB, L2-resident
__device__ float g_probs[PP];
__device__ float g_uz[FF], g_cz[FF], g_uh[FF], g_ch[FF];

__device__ __forceinline__ float tanh_fast(float x) {
    float r;
    asm("tanh.approx.f32 %0, %1;" : "=f"(r) : "f"(x));
    return r;
}

// pack two f32 into one f16x2 register (one cvt op)
__device__ __forceinline__ unsigned pack_h2(float lo, float hi) {
    unsigned r;
    asm("cvt.rn.f16x2.f32 %0, %1, %2;" : "=r"(r) : "f"(hi), "f"(lo));
    return r;
}

// 16B-aligned: 8 half adds in ONE RED op
__device__ __forceinline__ void red_h8(__half* p, unsigned r0, unsigned r1,
                                       unsigned r2, unsigned r3) {
    asm volatile("red.global.add.noftz.v4.f16x2 [%0], {%1,%2,%3,%4};"
                 :: "l"(p), "r"(r0), "r"(r1), "r"(r2), "r"(r3) : "memory");
}
__device__ __forceinline__ void red_h4(__half* p, unsigned r0, unsigned r1) {
    asm volatile("red.global.add.noftz.v2.f16x2 [%0], {%1,%2};"
                 :: "l"(p), "r"(r0), "r"(r1) : "memory");
}

// ---- fused: deg scatter (blocks 0..12499) + GRU-collapse/softmax precompute
//      (block 12500; independent of deg, consumed only by out_kernel) ----
__global__ void degprep_kernel(const int* __restrict__ ei,
                               const float* __restrict__ ew,
                               const float* __restrict__ att,
                               const float* __restrict__ wcz, const float* __restrict__ bcz,
                               const float* __restrict__ wch, const float* __restrict__ bch,
                               const float* __restrict__ wlz, const float* __restrict__ blz,
                               const float* __restrict__ wlh, const float* __restrict__ blh) {
    if (blockIdx.x == DEG_BLOCKS) {
        int k = threadIdx.x;
        if (k >= FF) return;
        float uz = 0.f, cz = blz[k], uh = 0.f, ch = blh[k];
#pragma unroll
        for (int j = 0; j < FF; j++) {
            float wz = wlz[j * FF + k], wh = wlh[j * FF + k];
            uz = fmaf(wcz[j], wz, uz);
            cz = fmaf(bcz[j], wz, cz);
            uh = fmaf(wch[j], wh, uh);
            ch = fmaf(bch[j], wh, ch);
        }
        g_uz[k] = uz; g_cz[k] = cz; g_uh[k] = uh; g_ch[k] = ch;
        if (k == 0) {
            float m = -1e30f;
            for (int p = 0; p < PP; p++) m = fmaxf(m, att[p]);
            float e[PP]; float s = 0.f;
            for (int p = 0; p < PP; p++) { e[p] = __expf(att[p] - m); s += e[p]; }
            float inv = 1.0f / s;
            for (int p = 0; p < PP; p++) g_probs[p] = e[p] * inv;
        }
        return;
    }
    int t = blockIdx.x * blockDim.x + threadIdx.x;
    if (t >= EE / 2) return;
    int2   d2 = ((const int2*)(ei + EE))[t];
    float2 w2 = ((const float2*)ew)[t];
    atomicAdd(&g_deg[d2.x], w2.x);
    atomicAdd(&g_deg[d2.y], w2.y);
}

// ---- dinv = rsqrt(deg + 1); self-clean g_deg for the next call ----
__global__ void dinv_kernel() {
    int n = blockIdx.x * blockDim.x + threadIdx.x;
    if (n >= NN) return;
    g_dinv[n] = rsqrtf(g_deg[n] + 1.0f);
    g_deg[n] = 0.f;
}

__device__ __forceinline__ void agg_one(int s, int d, float w, int bank,
                                        const float* __restrict__ x) {
    float nw = g_dinv[s] * w * g_dinv[d];
    const float4* xs = (const float4*)(x + (size_t)s * PP);
    float4 v0 = xs[0], v1 = xs[1], v2 = xs[2];
    unsigned r0 = pack_h2(nw * v0.x, nw * v0.y);
    unsigned r1 = pack_h2(nw * v0.z, nw * v0.w);
    unsigned r2 = pack_h2(nw * v1.x, nw * v1.y);
    unsigned r3 = pack_h2(nw * v1.z, nw * v1.w);
    unsigned r4 = pack_h2(nw * v2.x, nw * v2.y);
    unsigned r5 = pack_h2(nw * v2.z, nw * v2.w);
    __half* dst = g_agg + ((size_t)d * NBANK + bank) * ROWH;
    red_h8(dst, r0, r1, r2, r3);      // features 0..7  (16B aligned)
    red_h4(dst + 8, r4, r5);          // features 8..11 (16B offset)
}

// ---- agg: 2 edges/thread (occ ~88%), bank = edge & 7 ----
__global__ void __launch_bounds__(256) agg_kernel(const int* __restrict__ ei,
                                                  const float* __restrict__ ew,
                                                  const float* __restrict__ x) {
    int t = blockIdx.x * blockDim.x + threadIdx.x;
    if (t >= EE / 2) return;
    int2   s2 = ((const int2*)ei)[t];
    int2   d2 = ((const int2*)(ei + EE))[t];
    float2 w2 = ((const float2*)ew)[t];
    int b0 = (2 * t) & (NBANK - 1);
    agg_one(s2.x, d2.x, w2.x, b0,     x);
    agg_one(s2.y, d2.y, w2.y, b0 + 1, x);
}

// ---- node pass: 1 warp/node; coalesced u32 loads + shfl bank-sum ----
__global__ void out_kernel(const float* __restrict__ x,
                           const float* __restrict__ w_out,
                           const float* __restrict__ b_out,
                           float* __restrict__ out) {
    int warp = (blockIdx.x * blockDim.x + threadIdx.x) >> 5;
    int lane = threadIdx.x & 31;
    if (warp >= NN) return;
    int n = warp;

    // 64 u32 per node row (8 banks x 8 half2-words). u32 j: bank j/8, pair j%8.
    unsigned* row32 = (unsigned*)(g_agg + (size_t)n * NBANK * ROWH);
    unsigned A = row32[lane];        // bank lane/8     (0..3), pair lane%8
    unsigned B = row32[lane + 32];   // bank lane/8 + 4 (4..7), pair lane%8
    row32[lane] = 0u;                // self-clean for next call
    row32[lane + 32] = 0u;

    __half2 ha = *reinterpret_cast<__half2*>(&A);
    __half2 hb = *reinterpret_cast<__half2*>(&B);
    float c0 = __low2float(ha) + __low2float(hb);
    float c1 = __high2float(ha) + __high2float(hb);
    // sum the 4 bank-groups (lanes with equal lane%8)
    c0 += __shfl_xor_sync(0xffffffffu, c0, 8);
    c1 += __shfl_xor_sync(0xffffffffu, c1, 8);
    c0 += __shfl_xor_sync(0xffffffffu, c0, 16);
    c1 += __shfl_xor_sync(0xffffffffu, c1, 16);
    // every lane now holds pair (2*(lane%8), 2*(lane%8)+1) summed over 8 banks
    float f0 = __shfl_sync(0xffffffffu, c0, lane >> 1);
    float f1 = __shfl_sync(0xffffffffu, c1, lane >> 1);
    float bank_sum = (lane & 1) ? f1 : f0;   // feature `lane` total (lanes 0..11 valid)

    float dv = g_dinv[n];
    float sl = 0.f, pl = 0.f;
    if (lane < PP) {
        sl = fmaf(dv * dv, x[n * PP + lane], bank_sum);
        pl = g_probs[lane];
    }

    float uz = g_uz[lane], cz = g_cz[lane], uh = g_uh[lane], ch = g_ch[lane];
    float acc = 0.f;
#pragma unroll
    for (int p = 0; p < PP; p++) {
        float s  = __shfl_sync(0xffffffffu, sl, p);
        float pr = __shfl_sync(0xffffffffu, pl, p);
        float a = fmaf(s, uz, cz);
        float b = fmaf(s, uh, ch);
        // (1 - sigmoid(a)) = 0.5*(1 - tanh(a/2))
        float t1 = tanh_fast(0.5f * a);
        float t2 = tanh_fast(b);
        acc = fmaf(pr, 0.5f * (1.0f - t1) * t2, acc);
    }
    float v = fmaxf(acc, 0.0f) * w_out[lane];
#pragma unroll
    for (int o = 16; o; o >>= 1) v += __shfl_xor_sync(0xffffffffu, v, o);
    if (lane == 0) out[n] = v + b_out[0];
}

extern "C" void kernel_launch(void* const* d_in, const int* in_sizes, int n_in,
                              void* d_out, int out_size) {
    const float* x   = (const float*)d_in[0];
    const int*   ei  = (const int*)d_in[1];   // JAX w/o x64: int64 silently -> int32
    const float* ew  = (const float*)d_in[2];
    const float* att = (const float*)d_in[3];
    const float* wcz = (const float*)d_in[4];
    const float* bcz = (const float*)d_in[5];
    const float* wch = (const float*)d_in[8];
    const float* bch = (const float*)d_in[9];
    const float* wlz = (const float*)d_in[10];
    const float* blz = (const float*)d_in[11];
    const float* wlh = (const float*)d_in[14];
    const float* blh = (const float*)d_in[15];
    const float* wo  = (const float*)d_in[16];
    const float* bo  = (const float*)d_in[17];
    float*       out = (float*)d_out;

    // 4 kernels; ncu samples the 4th launch -> out_kernel gets profiled
    degprep_kernel<<<DEG_BLOCKS + 1, 256>>>(ei, ew, att, wcz, bcz, wch, bch,
                                            wlz, blz, wlh, blh);
    dinv_kernel<<<(NN + 255) / 256, 256>>>();
    agg_kernel<<<(EE / 2 + 255) / 256, 256>>>(ei, ew, x);
    out_kernel<<<(NN * 32 + 255) / 256, 256>>>(x, wo, bo, out);
}

// round 15
// speedup vs baseline: 1.2562x; 1.2562x over previous
#include <cuda_runtime.h>
#include <cuda_fp16.h>
#include <cstdint>

#define NN 100000
#define EE 6400000
#define PP 12
#define FF 32
#define ROWH 16    // halves per bank row -> 32B
#define NBANK 8    // accumulation banks per node (f16 rounding error ~ 1/B)
#define DEG_BLOCKS ((EE / 2 + 255) / 256)   // 12500

// scratch (device globals: no allocations allowed; BSS is zero-initialized,
// and each call re-zeroes its scratch after use => every call starts clean)
__device__ __align__(16) float  g_deg[NN];
__device__ __align__(16) float  g_dinv[NN];
__device__ __align__(16) __half g_agg[NN * NBANK * ROWH];   // 25.6 MB, L2-resident
__device__ float g_probs[PP];
__device__ float g_uz[FF], g_cz[FF], g_uh[FF], g_ch[FF];

__device__ __forceinline__ float tanh_fast(float x) {
    float r;
    asm("tanh.approx.f32 %0, %1;" : "=f"(r) : "f"(x));
    return r;
}

// pack two f32 into one f16x2 register (one cvt op)
__device__ __forceinline__ unsigned pack_h2(float lo, float hi) {
    unsigned r;
    asm("cvt.rn.f16x2.f32 %0, %1, %2;" : "=r"(r) : "f"(hi), "f"(lo));
    return r;
}

// 16B-aligned: 8 half adds in ONE RED op
__device__ __forceinline__ void red_h8(__half* p, unsigned r0, unsigned r1,
                                       unsigned r2, unsigned r3) {
    asm volatile("red.global.add.noftz.v4.f16x2 [%0], {%1,%2,%3,%4};"
                 :: "l"(p), "r"(r0), "r"(r1), "r"(r2), "r"(r3) : "memory");
}
__device__ __forceinline__ void red_h4(__half* p, unsigned r0, unsigned r1) {
    asm volatile("red.global.add.noftz.v2.f16x2 [%0], {%1,%2};"
                 :: "l"(p), "r"(r0), "r"(r1) : "memory");
}

// ---- fused: deg scatter (blocks 0..12499) + GRU-collapse/softmax precompute
//      (block 12500; independent of deg, consumed only by out_kernel) ----
__global__ void degprep_kernel(const int* __restrict__ ei,
                               const float* __restrict__ ew,
                               const float* __restrict__ att,
                               const float* __restrict__ wcz, const float* __restrict__ bcz,
                               const float* __restrict__ wch, const float* __restrict__ bch,
                               const float* __restrict__ wlz, const float* __restrict__ blz,
                               const float* __restrict__ wlh, const float* __restrict__ blh) {
    if (blockIdx.x == DEG_BLOCKS) {
        int k = threadIdx.x;
        if (k >= FF) return;
        float uz = 0.f, cz = blz[k], uh = 0.f, ch = blh[k];
#pragma unroll
        for (int j = 0; j < FF; j++) {
            float wz = wlz[j * FF + k], wh = wlh[j * FF + k];
            uz = fmaf(wcz[j], wz, uz);
            cz = fmaf(bcz[j], wz, cz);
            uh = fmaf(wch[j], wh, uh);
            ch = fmaf(bch[j], wh, ch);
        }
        g_uz[k] = uz; g_cz[k] = cz; g_uh[k] = uh; g_ch[k] = ch;
        if (k == 0) {
            float m = -1e30f;
            for (int p = 0; p < PP; p++) m = fmaxf(m, att[p]);
            float e[PP]; float s = 0.f;
            for (int p = 0; p < PP; p++) { e[p] = __expf(att[p] - m); s += e[p]; }
            float inv = 1.0f / s;
            for (int p = 0; p < PP; p++) g_probs[p] = e[p] * inv;
        }
        return;
    }
    int t = blockIdx.x * blockDim.x + threadIdx.x;
    if (t >= EE / 2) return;
    int2   d2 = ((const int2*)(ei + EE))[t];
    float2 w2 = ((const float2*)ew)[t];
    atomicAdd(&g_deg[d2.x], w2.x);
    atomicAdd(&g_deg[d2.y], w2.y);
}

// ---- dinv = rsqrt(deg + 1); self-clean g_deg for the next call ----
__global__ void dinv_kernel() {
    int n = blockIdx.x * blockDim.x + threadIdx.x;
    if (n >= NN) return;
    g_dinv[n] = rsqrtf(g_deg[n] + 1.0f);
    g_deg[n] = 0.f;
}

// accumulate dinv[s]*w*x (dinv[d] factored out -> applied once in out_kernel;
// saves one random gather per edge in the LTS-bound hot loop)
__device__ __forceinline__ void agg_one(int s, int d, float w, int bank,
                                        const float* __restrict__ x) {
    float nw = g_dinv[s] * w;
    const float4* xs = (const float4*)(x + (size_t)s * PP);
    float4 v0 = xs[0], v1 = xs[1], v2 = xs[2];
    unsigned r0 = pack_h2(nw * v0.x, nw * v0.y);
    unsigned r1 = pack_h2(nw * v0.z, nw * v0.w);
    unsigned r2 = pack_h2(nw * v1.x, nw * v1.y);
    unsigned r3 = pack_h2(nw * v1.z, nw * v1.w);
    unsigned r4 = pack_h2(nw * v2.x, nw * v2.y);
    unsigned r5 = pack_h2(nw * v2.z, nw * v2.w);
    __half* dst = g_agg + ((size_t)d * NBANK + bank) * ROWH;
    red_h8(dst, r0, r1, r2, r3);      // features 0..7  (16B aligned)
    red_h4(dst + 8, r4, r5);          // features 8..11 (16B offset)
}

// ---- agg: 2 edges/thread (occ ~88%), bank = edge & 7 ----
__global__ void __launch_bounds__(256) agg_kernel(const int* __restrict__ ei,
                                                  const float* __restrict__ ew,
                                                  const float* __restrict__ x) {
    int t = blockIdx.x * blockDim.x + threadIdx.x;
    if (t >= EE / 2) return;
    int2   s2 = ((const int2*)ei)[t];
    int2   d2 = ((const int2*)(ei + EE))[t];
    float2 w2 = ((const float2*)ew)[t];
    int b0 = (2 * t) & (NBANK - 1);
    agg_one(s2.x, d2.x, w2.x, b0,     x);
    agg_one(s2.y, d2.y, w2.y, b0 + 1, x);
}

// ---- node pass (R13-proven shape): 1 warp/node; lane = feature k ----
__global__ void out_kernel(const float* __restrict__ x,
                           const float* __restrict__ w_out,
                           const float* __restrict__ b_out,
                           float* __restrict__ out) {
    int warp = (blockIdx.x * blockDim.x + threadIdx.x) >> 5;
    int lane = threadIdx.x & 31;
    if (warp >= NN) return;
    int n = warp;
    float dv = g_dinv[n];
    const __half* row = g_agg + (size_t)n * NBANK * ROWH;
    float sl = 0.f, pl = 0.f;
    if (lane < PP) {
        float acc_f = 0.f;
#pragma unroll
        for (int b = 0; b < NBANK; b++)
            acc_f += __half2float(row[b * ROWH + lane]);
        // bank sum holds dinv_s*w*x ; apply the factored-out dinv_d here
        sl = fmaf(dv, acc_f, dv * dv * x[n * PP + lane]);
        pl = g_probs[lane];
    }
    // self-clean the node's 8 bank rows (128 halves = 64 u32; 2 per lane)
    ((unsigned*)row)[lane] = 0u;
    ((unsigned*)row)[lane + 32] = 0u;

    float uz = g_uz[lane], cz = g_cz[lane], uh = g_uh[lane], ch = g_ch[lane];
    float acc = 0.f;
#pragma unroll
    for (int p = 0; p < PP; p++) {
        float s  = __shfl_sync(0xffffffffu, sl, p);
        float pr = __shfl_sync(0xffffffffu, pl, p);
        float a = fmaf(s, uz, cz);
        float b = fmaf(s, uh, ch);
        // (1 - sigmoid(a)) = 0.5*(1 - tanh(a/2))
        float t1 = tanh_fast(0.5f * a);
        float t2 = tanh_fast(b);
        acc = fmaf(pr, 0.5f * (1.0f - t1) * t2, acc);
    }
    float v = fmaxf(acc, 0.0f) * w_out[lane];
#pragma unroll
    for (int o = 16; o; o >>= 1) v += __shfl_xor_sync(0xffffffffu, v, o);
    if (lane == 0) out[n] = v + b_out[0];
}

extern "C" void kernel_launch(void* const* d_in, const int* in_sizes, int n_in,
                              void* d_out, int out_size) {
    const float* x   = (const float*)d_in[0];
    const int*   ei  = (const int*)d_in[1];   // JAX w/o x64: int64 silently -> int32
    const float* ew  = (const float*)d_in[2];
    const float* att = (const float*)d_in[3];
    const float* wcz = (const float*)d_in[4];
    const float* bcz = (const float*)d_in[5];
    const float* wch = (const float*)d_in[8];
    const float* bch = (const float*)d_in[9];
    const float* wlz = (const float*)d_in[10];
    const float* blz = (const float*)d_in[11];
    const float* wlh = (const float*)d_in[14];
    const float* blh = (const float*)d_in[15];
    const float* wo  = (const float*)d_in[16];
    const float* bo  = (const float*)d_in[17];
    float*       out = (float*)d_out;

    degprep_kernel<<<DEG_BLOCKS + 1, 256>>>(ei, ew, att, wcz, bcz, wch, bch,
                                            wlz, blz, wlh, blh);
    dinv_kernel<<<(NN + 255) / 256, 256>>>();
    agg_kernel<<<(EE / 2 + 255) / 256, 256>>>(ei, ew, x);
    out_kernel<<<(NN * 32 + 255) / 256, 256>>>(x, wo, bo, out);
}

// round 16
// speedup vs baseline: 1.2570x; 1.0007x over previous
#include <cuda_runtime.h>
#include <cuda_fp16.h>
#include <cstdint>

#define NN 100000
#define EE 6400000
#define PP 12
#define FF 32
#define ROWH 16    // halves per bank row -> 32B
#define NBANK 8    // accumulation banks per node (f16 rounding error ~ 1/B)
#define DEG_BLOCKS ((EE / 2 + 255) / 256)   // 12500

// scratch (device globals: no allocations allowed; BSS is zero-initialized,
// and each call re-zeroes its scratch after use => every call starts clean)
__device__ __align__(16) float  g_deg[NN];
__device__ __align__(16) __half g_agg[NN * NBANK * ROWH];   // 25.6 MB, L2-resident
__device__ float g_probs[PP];                // pre-scaled by 0.5
__device__ float g_uz[FF], g_cz[FF];         // pre-scaled by 0.5 (for tanh(a/2))
__device__ float g_uh[FF], g_ch[FF];

__device__ __forceinline__ float tanh_fast(float x) {
    float r;
    asm("tanh.approx.f32 %0, %1;" : "=f"(r) : "f"(x));
    return r;
}

// pack two f32 into one f16x2 register (one cvt op)
__device__ __forceinline__ unsigned pack_h2(float lo, float hi) {
    unsigned r;
    asm("cvt.rn.f16x2.f32 %0, %1, %2;" : "=r"(r) : "f"(hi), "f"(lo));
    return r;
}

// 16B-aligned: 8 half adds in ONE RED op
__device__ __forceinline__ void red_h8(__half* p, unsigned r0, unsigned r1,
                                       unsigned r2, unsigned r3) {
    asm volatile("red.global.add.noftz.v4.f16x2 [%0], {%1,%2,%3,%4};"
                 :: "l"(p), "r"(r0), "r"(r1), "r"(r2), "r"(r3) : "memory");
}
__device__ __forceinline__ void red_h4(__half* p, unsigned r0, unsigned r1) {
    asm volatile("red.global.add.noftz.v2.f16x2 [%0], {%1,%2};"
                 :: "l"(p), "r"(r0), "r"(r1) : "memory");
}

// ---- fused: deg scatter (blocks 0..12499) + GRU-collapse/softmax precompute
//      (block 12500; independent of deg, consumed only by out_kernel) ----
__global__ void degprep_kernel(const int* __restrict__ ei,
                               const float* __restrict__ ew,
                               const float* __restrict__ att,
                               const float* __restrict__ wcz, const float* __restrict__ bcz,
                               const float* __restrict__ wch, const float* __restrict__ bch,
                               const float* __restrict__ wlz, const float* __restrict__ blz,
                               const float* __restrict__ wlh, const float* __restrict__ blh) {
    if (blockIdx.x == DEG_BLOCKS) {
        int k = threadIdx.x;
        if (k >= FF) return;
        float uz = 0.f, cz = blz[k], uh = 0.f, ch = blh[k];
#pragma unroll
        for (int j = 0; j < FF; j++) {
            float wz = wlz[j * FF + k], wh = wlh[j * FF + k];
            uz = fmaf(wcz[j], wz, uz);
            cz = fmaf(bcz[j], wz, cz);
            uh = fmaf(wch[j], wh, uh);
            ch = fmaf(bch[j], wh, ch);
        }
        g_uz[k] = 0.5f * uz;   // pre-halved: tanh(a/2) argument
        g_cz[k] = 0.5f * cz;
        g_uh[k] = uh;
        g_ch[k] = ch;
        if (k == 0) {
            float m = -1e30f;
            for (int p = 0; p < PP; p++) m = fmaxf(m, att[p]);
            float e[PP]; float s = 0.f;
            for (int p = 0; p < PP; p++) { e[p] = __expf(att[p] - m); s += e[p]; }
            float inv = 0.5f / s;   // fold the 0.5*(1-t1)*t2 factor into probs
            for (int p = 0; p < PP; p++) g_probs[p] = e[p] * inv;
        }
        return;
    }
    int t = blockIdx.x * blockDim.x + threadIdx.x;
    if (t >= EE / 2) return;
    int2   d2 = ((const int2*)(ei + EE))[t];
    float2 w2 = ((const float2*)ew)[t];
    atomicAdd(&g_deg[d2.x], w2.x);
    atomicAdd(&g_deg[d2.y], w2.y);
}

// accumulate dinv_s*w*x (dinv_d factored out -> applied once in out_kernel).
// dinv_s computed inline from g_deg (agg has 95% issue headroom; kills the
// separate dinv kernel + its launch gap).
__device__ __forceinline__ void agg_one(int s, int d, float w,
                                        int bank, const float* __restrict__ x) {
    float nw = rsqrtf(g_deg[s] + 1.0f) * w;
    const float4* xs = (const float4*)(x + (size_t)s * PP);
    float4 v0 = xs[0], v1 = xs[1], v2 = xs[2];
    unsigned r0 = pack_h2(nw * v0.x, nw * v0.y);
    unsigned r1 = pack_h2(nw * v0.z, nw * v0.w);
    unsigned r2 = pack_h2(nw * v1.x, nw * v1.y);
    unsigned r3 = pack_h2(nw * v1.z, nw * v1.w);
    unsigned r4 = pack_h2(nw * v2.x, nw * v2.y);
    unsigned r5 = pack_h2(nw * v2.z, nw * v2.w);
    __half* dst = g_agg + ((size_t)d * NBANK + bank) * ROWH;
    red_h8(dst, r0, r1, r2, r3);      // features 0..7  (16B aligned)
    red_h4(dst + 8, r4, r5);          // features 8..11 (16B offset)
}

// ---- agg: 2 edges/thread (occ ~88%), bank = edge & 7 ----
__global__ void __launch_bounds__(256) agg_kernel(const int* __restrict__ ei,
                                                  const float* __restrict__ ew,
                                                  const float* __restrict__ x) {
    int t = blockIdx.x * blockDim.x + threadIdx.x;
    if (t >= EE / 2) return;
    int2   s2 = ((const int2*)ei)[t];
    int2   d2 = ((const int2*)(ei + EE))[t];
    float2 w2 = ((const float2*)ew)[t];
    int b0 = (2 * t) & (NBANK - 1);
    agg_one(s2.x, d2.x, w2.x, b0,     x);
    agg_one(s2.y, d2.y, w2.y, b0 + 1, x);
}

// ---- node pass: 1 warp/node; lane = feature k; self-clean agg + deg ----
__global__ void out_kernel(const float* __restrict__ x,
                           const float* __restrict__ w_out,
                           const float* __restrict__ b_out,
                           float* __restrict__ out) {
    int warp = (blockIdx.x * blockDim.x + threadIdx.x) >> 5;
    int lane = threadIdx.x & 31;
    if (warp >= NN) return;
    int n = warp;
    float dv = rsqrtf(g_deg[n] + 1.0f);
    const __half* row = g_agg + (size_t)n * NBANK * ROWH;
    float sl = 0.f;
    if (lane < PP) {
        float acc_f = 0.f;
#pragma unroll
        for (int b = 0; b < NBANK; b++)
            acc_f += __half2float(row[b * ROWH + lane]);
        // bank sum holds dinv_s*w*x ; apply the factored-out dinv_d here
        sl = fmaf(dv, acc_f, dv * dv * x[n * PP + lane]);
    }
    // self-clean scratch for the next call
    ((unsigned*)row)[lane] = 0u;
    ((unsigned*)row)[lane + 32] = 0u;
    if (lane == 16) g_deg[n] = 0.f;

    // hoist probs into registers (no per-iter shfl for pr)
    float pr[PP];
#pragma unroll
    for (int p = 0; p < PP; p++) pr[p] = g_probs[p];   // pre-scaled by 0.5

    float uz = g_uz[lane], cz = g_cz[lane];   // pre-halved
    float uh = g_uh[lane], ch = g_ch[lane];
    float acc = 0.f;
#pragma unroll
    for (int p = 0; p < PP; p++) {
        float s  = __shfl_sync(0xffffffffu, sl, p);
        float a = fmaf(s, uz, cz);            // = (s*Uz + Cz)/2
        float b = fmaf(s, uh, ch);
        float t1 = tanh_fast(a);              // tanh of half-arg = sigmoid form
        float t2 = tanh_fast(b);
        acc = fmaf(pr[p], (1.0f - t1) * t2, acc);   // pr already has the 0.5
    }
    float v = fmaxf(acc, 0.0f) * w_out[lane];
#pragma unroll
    for (int o = 16; o; o >>= 1) v += __shfl_xor_sync(0xffffffffu, v, o);
    if (lane == 0) out[n] = v + b_out[0];
}

extern "C" void kernel_launch(void* const* d_in, const int* in_sizes, int n_in,
                              void* d_out, int out_size) {
    const float* x   = (const float*)d_in[0];
    const int*   ei  = (const int*)d_in[1];   // JAX w/o x64: int64 silently -> int32
    const float* ew  = (const float*)d_in[2];
    const float* att = (const float*)d_in[3];
    const float* wcz = (const float*)d_in[4];
    const float* bcz = (const float*)d_in[5];
    const float* wch = (const float*)d_in[8];
    const float* bch = (const float*)d_in[9];
    const float* wlz = (const float*)d_in[10];
    const float* blz = (const float*)d_in[11];
    const float* wlh = (const float*)d_in[14];
    const float* blh = (const float*)d_in[15];
    const float* wo  = (const float*)d_in[16];
    const float* bo  = (const float*)d_in[17];
    float*       out = (float*)d_out;

    degprep_kernel<<<DEG_BLOCKS + 1, 256>>>(ei, ew, att, wcz, bcz, wch, bch,
                                            wlz, blz, wlh, blh);
    agg_kernel<<<(EE / 2 + 255) / 256, 256>>>(ei, ew, x);
    out_kernel<<<(NN * 32 + 255) / 256, 256>>>(x, wo, bo, out);
}

// round 17
// speedup vs baseline: 1.2608x; 1.0030x over previous
#include <cuda_runtime.h>
#include <cuda_fp16.h>
#include <cstdint>

#define NN 100000
#define EE 6400000
#define PP 12
#define FF 32
#define ROWH 16    // halves per bank row -> 32B
#define NBANK 8    // accumulation banks per node (f16 rounding error ~ 1/B)
#define DEG_BLOCKS ((EE / 4 + 255) / 256)   // 6250

// scratch (device globals: no allocations allowed; BSS is zero-initialized,
// and each call re-zeroes its scratch after use => every call starts clean)
__device__ __align__(16) float  g_deg[NN];
__device__ __align__(16) __half g_agg[NN * NBANK * ROWH];   // 25.6 MB, L2-resident
__device__ float g_probs[PP];                // pre-scaled by 0.5
__device__ float g_uz[FF], g_cz[FF];         // pre-scaled by 0.5 (for tanh(a/2))
__device__ float g_uh[FF], g_ch[FF];

__device__ __forceinline__ float tanh_fast(float x) {
    float r;
    asm("tanh.approx.f32 %0, %1;" : "=f"(r) : "f"(x));
    return r;
}

// pack two f32 into one f16x2 register (one cvt op)
__device__ __forceinline__ unsigned pack_h2(float lo, float hi) {
    unsigned r;
    asm("cvt.rn.f16x2.f32 %0, %1, %2;" : "=r"(r) : "f"(hi), "f"(lo));
    return r;
}

// 16B-aligned: 8 half adds in ONE RED op
__device__ __forceinline__ void red_h8(__half* p, unsigned r0, unsigned r1,
                                       unsigned r2, unsigned r3) {
    asm volatile("red.global.add.noftz.v4.f16x2 [%0], {%1,%2,%3,%4};"
                 :: "l"(p), "r"(r0), "r"(r1), "r"(r2), "r"(r3) : "memory");
}
__device__ __forceinline__ void red_h4(__half* p, unsigned r0, unsigned r1) {
    asm volatile("red.global.add.noftz.v2.f16x2 [%0], {%1,%2};"
                 :: "l"(p), "r"(r0), "r"(r1) : "memory");
}

// ---- fused: deg scatter (blocks 0..6249; 4 edges/thread for MLP) +
//      GRU-collapse/softmax precompute (block 6250) ----
__global__ void degprep_kernel(const int* __restrict__ ei,
                               const float* __restrict__ ew,
                               const float* __restrict__ att,
                               const float* __restrict__ wcz, const float* __restrict__ bcz,
                               const float* __restrict__ wch, const float* __restrict__ bch,
                               const float* __restrict__ wlz, const float* __restrict__ blz,
                               const float* __restrict__ wlh, const float* __restrict__ blh) {
    if (blockIdx.x == DEG_BLOCKS) {
        int k = threadIdx.x;
        if (k >= FF) return;
        float uz = 0.f, cz = blz[k], uh = 0.f, ch = blh[k];
#pragma unroll
        for (int j = 0; j < FF; j++) {
            float wz = wlz[j * FF + k], wh = wlh[j * FF + k];
            uz = fmaf(wcz[j], wz, uz);
            cz = fmaf(bcz[j], wz, cz);
            uh = fmaf(wch[j], wh, uh);
            ch = fmaf(bch[j], wh, ch);
        }
        g_uz[k] = 0.5f * uz;   // pre-halved: tanh(a/2) argument
        g_cz[k] = 0.5f * cz;
        g_uh[k] = uh;
        g_ch[k] = ch;
        if (k == 0) {
            float m = -1e30f;
            for (int p = 0; p < PP; p++) m = fmaxf(m, att[p]);
            float e[PP]; float s = 0.f;
            for (int p = 0; p < PP; p++) { e[p] = __expf(att[p] - m); s += e[p]; }
            float inv = 0.5f / s;   // fold the 0.5*(1-t1)*t2 factor into probs
            for (int p = 0; p < PP; p++) g_probs[p] = e[p] * inv;
        }
        return;
    }
    int t = blockIdx.x * blockDim.x + threadIdx.x;
    if (t >= EE / 4) return;
    int4   d4 = ((const int4*)(ei + EE))[t];
    float4 w4 = ((const float4*)ew)[t];
    atomicAdd(&g_deg[d4.x], w4.x);
    atomicAdd(&g_deg[d4.y], w4.y);
    atomicAdd(&g_deg[d4.z], w4.z);
    atomicAdd(&g_deg[d4.w], w4.w);
}

// accumulate dinv_s*w*x (dinv_d factored out -> applied once in out_kernel).
// dinv_s computed inline from g_deg (agg has 95% issue headroom).
__device__ __forceinline__ void agg_one(int s, int d, float w,
                                        int bank, const float* __restrict__ x) {
    float nw = rsqrtf(g_deg[s] + 1.0f) * w;
    const float4* xs = (const float4*)(x + (size_t)s * PP);
    float4 v0 = xs[0], v1 = xs[1], v2 = xs[2];
    unsigned r0 = pack_h2(nw * v0.x, nw * v0.y);
    unsigned r1 = pack_h2(nw * v0.z, nw * v0.w);
    unsigned r2 = pack_h2(nw * v1.x, nw * v1.y);
    unsigned r3 = pack_h2(nw * v1.z, nw * v1.w);
    unsigned r4 = pack_h2(nw * v2.x, nw * v2.y);
    unsigned r5 = pack_h2(nw * v2.z, nw * v2.w);
    __half* dst = g_agg + ((size_t)d * NBANK + bank) * ROWH;
    red_h8(dst, r0, r1, r2, r3);      // features 0..7  (16B aligned)
    red_h4(dst + 8, r4, r5);          // features 8..11 (16B offset)
}

// ---- agg: 2 edges/thread (occ ~88%), bank = edge & 7 ----
__global__ void __launch_bounds__(256) agg_kernel(const int* __restrict__ ei,
                                                  const float* __restrict__ ew,
                                                  const float* __restrict__ x) {
    int t = blockIdx.x * blockDim.x + threadIdx.x;
    if (t >= EE / 2) return;
    int2   s2 = ((const int2*)ei)[t];
    int2   d2 = ((const int2*)(ei + EE))[t];
    float2 w2 = ((const float2*)ew)[t];
    int b0 = (2 * t) & (NBANK - 1);
    agg_one(s2.x, d2.x, w2.x, b0,     x);
    agg_one(s2.y, d2.y, w2.y, b0 + 1, x);
}

// ---- node pass: 1 warp/node; lane = feature k; self-clean agg + deg ----
__global__ void out_kernel(const float* __restrict__ x,
                           const float* __restrict__ w_out,
                           const float* __restrict__ b_out,
                           float* __restrict__ out) {
    int warp = (blockIdx.x * blockDim.x + threadIdx.x) >> 5;
    int lane = threadIdx.x & 31;
    if (warp >= NN) return;
    int n = warp;
    float dv = rsqrtf(g_deg[n] + 1.0f);
    const __half* row = g_agg + (size_t)n * NBANK * ROWH;
    float sl = 0.f;
    if (lane < PP) {
        float acc_f = 0.f;
#pragma unroll
        for (int b = 0; b < NBANK; b++)
            acc_f += __half2float(row[b * ROWH + lane]);
        // bank sum holds dinv_s*w*x ; apply the factored-out dinv_d here
        sl = fmaf(dv, acc_f, dv * dv * x[n * PP + lane]);
    }
    // self-clean scratch for the next call
    ((unsigned*)row)[lane] = 0u;
    ((unsigned*)row)[lane + 32] = 0u;
    if (lane == 16) g_deg[n] = 0.f;

    // hoist probs into registers (no per-iter shfl for pr)
    float pr[PP];
#pragma unroll
    for (int p = 0; p < PP; p++) pr[p] = g_probs[p];   // pre-scaled by 0.5

    float uz = g_uz[lane], cz = g_cz[lane];   // pre-halved
    float uh = g_uh[lane], ch = g_ch[lane];
    float acc = 0.f;
#pragma unroll
    for (int p = 0; p < PP; p++) {
        float s  = __shfl_sync(0xffffffffu, sl, p);
        float a = fmaf(s, uz, cz);            // = (s*Uz + Cz)/2
        float b = fmaf(s, uh, ch);
        float t1 = tanh_fast(a);              // tanh of half-arg = sigmoid form
        float t2 = tanh_fast(b);
        acc = fmaf(pr[p], (1.0f - t1) * t2, acc);   // pr already has the 0.5
    }
    float v = fmaxf(acc, 0.0f) * w_out[lane];
#pragma unroll
    for (int o = 16; o; o >>= 1) v += __shfl_xor_sync(0xffffffffu, v, o);
    if (lane == 0) out[n] = v + b_out[0];
}

extern "C" void kernel_launch(void* const* d_in, const int* in_sizes, int n_in,
                              void* d_out, int out_size) {
    const float* x   = (const float*)d_in[0];
    const int*   ei  = (const int*)d_in[1];   // JAX w/o x64: int64 silently -> int32
    const float* ew  = (const float*)d_in[2];
    const float* att = (const float*)d_in[3];
    const float* wcz = (const float*)d_in[4];
    const float* bcz = (const float*)d_in[5];
    const float* wch = (const float*)d_in[8];
    const float* bch = (const float*)d_in[9];
    const float* wlz = (const float*)d_in[10];
    const float* blz = (const float*)d_in[11];
    const float* wlh = (const float*)d_in[14];
    const float* blh = (const float*)d_in[15];
    const float* wo  = (const float*)d_in[16];
    const float* bo  = (const float*)d_in[17];
    float*       out = (float*)d_out;

    degprep_kernel<<<DEG_BLOCKS + 1, 256>>>(ei, ew, att, wcz, bcz, wch, bch,
                                            wlz, blz, wlh, blh);
    agg_kernel<<<(EE / 2 + 255) / 256, 256>>>(ei, ew, x);
    out_kernel<<<(NN * 32 + 255) / 256, 256>>>(x, wo, bo, out);
}